// round 2
// baseline (speedup 1.0000x reference)
#include <cuda_runtime.h>

#define NB 8
#define NT 2048
#define ND 256
#define BT (NB*NT)

// ---------------- scratch (static device globals; no allocation) ----------------
__device__ float g_vb1[BT*ND];
__device__ float g_vb2[BT*ND];
__device__ float g_ab1[BT*ND];
__device__ float g_ab2[BT*ND];
__device__ float g_beta[(size_t)NB*NT*NT];     // 134 MB
__device__ float g_rowpart[16*NB*NT];          // per ab-tile partial row sums
__device__ float g_colpart[16*NB*NT];          // per vb-tile partial col sums
__device__ float g_rowsum[NB*NT];
__device__ float g_colsum[NB*NT];
__device__ float g_apos[BT*ND];
__device__ float g_vpos[BT*ND];

// ---------------- shared GEMM core: BM=BN=128, BK=16, 256 thr, 8x8 micro ----------------
// Tiles stored K-major: S[16][132] (pad 4 keeps float4 rows 16B-aligned).
// Thread (tx=tid&15, ty=tid>>4) owns rows {ty*4..+3, 64+ty*4..+3} x cols {tx*4..+3, 64+tx*4..+3}.

__device__ __forceinline__ void mm_inner(const float (*As)[132], const float (*Bs)[132],
                                         float acc[8][8], int tx, int ty) {
#pragma unroll
    for (int kk = 0; kk < 16; kk++) {
        float ar[8], br[8];
        *(float4*)&ar[0] = *(const float4*)&As[kk][ty * 4];
        *(float4*)&ar[4] = *(const float4*)&As[kk][64 + ty * 4];
        *(float4*)&br[0] = *(const float4*)&Bs[kk][tx * 4];
        *(float4*)&br[4] = *(const float4*)&Bs[kk][64 + tx * 4];
#pragma unroll
        for (int i = 0; i < 8; i++)
#pragma unroll
            for (int j = 0; j < 8; j++)
                acc[i][j] = fmaf(ar[i], br[j], acc[i][j]);
    }
}

// load a [128 rows x 16 k] tile from row-major G (k contiguous), transposed into S[k][row]
__device__ __forceinline__ void load_T(float (*S)[132], const float* __restrict__ G,
                                       int rowBase, int ld, int k0, int tid) {
    int kk = tid & 15;
    int r0 = tid >> 4;
#pragma unroll
    for (int i = 0; i < 8; i++) {
        int r = r0 + i * 16;
        S[kk][r] = G[(size_t)(rowBase + r) * ld + k0 + kk];
    }
}

// load a [16 k x 128 n] tile from row-major G into S[k][n]
__device__ __forceinline__ void load_N(float (*S)[132], const float* __restrict__ G,
                                       int k0, int ld, int nBase, int tid) {
    int n = tid & 127;
    int kb = tid >> 7;
#pragma unroll
    for (int i = 0; i < 8; i++) {
        int kk = kb + i * 2;
        S[kk][n] = G[(size_t)(k0 + kk) * ld + nBase + n];
    }
}

// ---------------- stage 1: four input GEMMs + relu ----------------
__global__ __launch_bounds__(256) void k_in_gemm(const float* __restrict__ vf, const float* __restrict__ af,
                                                 const float* __restrict__ Wv1, const float* __restrict__ Wv2,
                                                 const float* __restrict__ Wa1, const float* __restrict__ Wa2) {
    __shared__ __align__(16) float As[16][132];
    __shared__ __align__(16) float Bs[16][132];
    int z = blockIdx.z;
    const float* X = (z < 2) ? vf : af;
    const float* W = (z == 0) ? Wv1 : (z == 1) ? Wv2 : (z == 2) ? Wa1 : Wa2;
    float* Y = (z == 0) ? g_vb1 : (z == 1) ? g_vb2 : (z == 2) ? g_ab1 : g_ab2;
    int mb = blockIdx.y * 128, nb = blockIdx.x * 128;
    int tid = threadIdx.x, tx = tid & 15, ty = tid >> 4;
    float acc[8][8] = {};
    for (int k0 = 0; k0 < ND; k0 += 16) {
        load_T(As, X, mb, ND, k0, tid);
        load_N(Bs, W, k0, ND, nb, tid);
        __syncthreads();
        mm_inner(As, Bs, acc, tx, ty);
        __syncthreads();
    }
#pragma unroll
    for (int ih = 0; ih < 2; ih++)
#pragma unroll
        for (int i = 0; i < 4; i++) {
            int m = mb + ih * 64 + ty * 4 + i;
#pragma unroll
            for (int jh = 0; jh < 2; jh++) {
                float4 o;
                o.x = fmaxf(acc[ih * 4 + i][jh * 4 + 0], 0.f);
                o.y = fmaxf(acc[ih * 4 + i][jh * 4 + 1], 0.f);
                o.z = fmaxf(acc[ih * 4 + i][jh * 4 + 2], 0.f);
                o.w = fmaxf(acc[ih * 4 + i][jh * 4 + 3], 0.f);
                *(float4*)&Y[(size_t)m * ND + nb + jh * 64 + tx * 4] = o;
            }
        }
}

// ---------------- stage 2: beta = relu((Vb2 @ Ab1^T)/16), fused partial row/col sums ----------------
__global__ __launch_bounds__(256) void k_beta_g() {
    __shared__ __align__(16) float As[16][132];
    __shared__ __align__(16) float Bs[16][132];
    int b = blockIdx.z;
    const float* V = g_vb2 + (size_t)b * NT * ND;
    const float* A = g_ab1 + (size_t)b * NT * ND;
    float* Bo = g_beta + (size_t)b * NT * NT;
    int vb = blockIdx.y * 128, ab = blockIdx.x * 128;
    int tid = threadIdx.x, tx = tid & 15, ty = tid >> 4;
    float acc[8][8] = {};
    for (int k0 = 0; k0 < ND; k0 += 16) {
        load_T(As, V, vb, ND, k0, tid);
        load_T(Bs, A, ab, ND, k0, tid);
        __syncthreads();
        mm_inner(As, Bs, acc, tx, ty);
        __syncthreads();
    }
    const float sc = 0.0625f;  // 1/sqrt(256)
    // relu+scale in-register, store, and build per-thread row/col partials
    float rsum[8];   // per owned row: sum over this thread's 8 cols
#pragma unroll
    for (int i = 0; i < 8; i++) rsum[i] = 0.f;
#pragma unroll
    for (int ih = 0; ih < 2; ih++)
#pragma unroll
        for (int i = 0; i < 4; i++) {
            int r = ih * 4 + i;
            int m = vb + ih * 64 + ty * 4 + i;
#pragma unroll
            for (int jh = 0; jh < 2; jh++) {
                float4 o;
                o.x = fmaxf(acc[r][jh * 4 + 0] * sc, 0.f);
                o.y = fmaxf(acc[r][jh * 4 + 1] * sc, 0.f);
                o.z = fmaxf(acc[r][jh * 4 + 2] * sc, 0.f);
                o.w = fmaxf(acc[r][jh * 4 + 3] * sc, 0.f);
                acc[r][jh * 4 + 0] = o.x; acc[r][jh * 4 + 1] = o.y;
                acc[r][jh * 4 + 2] = o.z; acc[r][jh * 4 + 3] = o.w;
                rsum[r] += (o.x + o.y) + (o.z + o.w);
                *(float4*)&Bo[(size_t)m * NT + ab + jh * 64 + tx * 4] = o;
            }
        }
    // --- row partials: reduce across tx (16 contiguous lanes in a half-warp) ---
#pragma unroll
    for (int o = 1; o < 16; o <<= 1)
#pragma unroll
        for (int i = 0; i < 8; i++) rsum[i] += __shfl_xor_sync(0xffffffffu, rsum[i], o);
    if (tx == 0) {
        float* rp = g_rowpart + ((size_t)blockIdx.x * NB + b) * NT + vb;
#pragma unroll
        for (int ih = 0; ih < 2; ih++)
#pragma unroll
            for (int i = 0; i < 4; i++) rp[ih * 64 + ty * 4 + i] = rsum[ih * 4 + i];
    }
    // --- col partials: smem reduce across ty (reuse As) ---
    float* scol = &As[0][0];  // [16 ty][128 cols], stride 128
    __syncthreads();
#pragma unroll
    for (int jh = 0; jh < 2; jh++)
#pragma unroll
        for (int j = 0; j < 4; j++) {
            float s = 0.f;
#pragma unroll
            for (int i = 0; i < 8; i++) s += acc[i][jh * 4 + j];
            scol[ty * 128 + jh * 64 + tx * 4 + j] = s;
        }
    __syncthreads();
    if (tid < 128) {
        float s = 0.f;
#pragma unroll
        for (int t = 0; t < 16; t++) s += scol[t * 128 + tid];
        g_colpart[((size_t)blockIdx.y * NB + b) * NT + ab + tid] = s;
    }
}

// ---------------- stage 2b: tiny final reductions (16 partials each) ----------------
__global__ __launch_bounds__(256) void k_sumred() {
    int i = blockIdx.x * 256 + threadIdx.x;  // 0 .. NB*NT-1
    float r = 0.f, c = 0.f;
#pragma unroll
    for (int t = 0; t < 16; t++) {
        r += g_rowpart[(size_t)t * NB * NT + i];
        c += g_colpart[(size_t)t * NB * NT + i];
    }
    g_rowsum[i] = r;
    g_colsum[i] = c;
}

// ---------------- stage 3: gamma-GEMMs (normalize+threshold fused into A-load) ----------------
// mode 0: a_pos[v,h] = sum_a thresh(beta[v,a]/rowsum[v]) * a_b2[a,h]
// mode 1: v_pos[a,h] = sum_v thresh(beta[v,a]/colsum[a]) * v_b1[v,h]
__global__ __launch_bounds__(256) void k_pos(const float* __restrict__ thr_p) {
    __shared__ __align__(16) float As[16][132];
    __shared__ __align__(16) float Bs[16][132];
    __shared__ float inv[128];
    int z = blockIdx.z;
    int b = z >> 1, mode = z & 1;
    float thr = thr_p[0];
    const float* Bt = g_beta + (size_t)b * NT * NT;
    const float* Bm = (mode == 0) ? (g_ab2 + (size_t)b * NT * ND) : (g_vb1 + (size_t)b * NT * ND);
    float* Out = (mode == 0) ? (g_apos + (size_t)b * NT * ND) : (g_vpos + (size_t)b * NT * ND);
    const float* sums = (mode == 0) ? (g_rowsum + b * NT) : (g_colsum + b * NT);
    int mb = blockIdx.y * 128, nb = blockIdx.x * 128;
    int tid = threadIdx.x, tx = tid & 15, ty = tid >> 4;
    if (tid < 128) inv[tid] = 1.0f / (sums[mb + tid] + 1e-8f);
    __syncthreads();
    float acc[8][8] = {};
    for (int k0 = 0; k0 < NT; k0 += 16) {
        if (mode == 0) {
            int kk = tid & 15, r0 = tid >> 4;
#pragma unroll
            for (int i = 0; i < 8; i++) {
                int r = r0 + i * 16;
                float v = Bt[(size_t)(mb + r) * NT + k0 + kk] * inv[r];
                As[kk][r] = (v > thr) ? v : 0.f;
            }
        } else {
            int n = tid & 127, kb = tid >> 7;
            float iv = inv[n];
#pragma unroll
            for (int i = 0; i < 8; i++) {
                int kk = kb + i * 2;
                float v = Bt[(size_t)(k0 + kk) * NT + mb + n] * iv;
                As[kk][n] = (v > thr) ? v : 0.f;
            }
        }
        load_N(Bs, Bm, k0, ND, nb, tid);
        __syncthreads();
        mm_inner(As, Bs, acc, tx, ty);
        __syncthreads();
    }
#pragma unroll
    for (int ih = 0; ih < 2; ih++)
#pragma unroll
        for (int i = 0; i < 4; i++) {
            int m = mb + ih * 64 + ty * 4 + i;
#pragma unroll
            for (int jh = 0; jh < 2; jh++) {
                float4 o;
                o.x = acc[ih * 4 + i][jh * 4 + 0];
                o.y = acc[ih * 4 + i][jh * 4 + 1];
                o.z = acc[ih * 4 + i][jh * 4 + 2];
                o.w = acc[ih * 4 + i][jh * 4 + 3];
                *(float4*)&Out[(size_t)m * ND + nb + jh * 64 + tx * 4] = o;
            }
        }
}

// ---------------- stage 4: residual + dual LayerNorm + average ----------------
__global__ __launch_bounds__(256) void k_final(const float* __restrict__ vf, const float* __restrict__ af,
                                               const float* __restrict__ lng, const float* __restrict__ lnb,
                                               float* __restrict__ out) {
    int row = blockIdx.x;
    int d = threadIdx.x;
    size_t idx = (size_t)row * ND + d;
    float x1 = vf[idx] + g_apos[idx];
    float x2 = af[idx] + g_vpos[idx];
    float s1 = x1, q1 = x1 * x1, s2 = x2, q2 = x2 * x2;
#pragma unroll
    for (int o = 16; o; o >>= 1) {
        s1 += __shfl_xor_sync(0xffffffffu, s1, o);
        q1 += __shfl_xor_sync(0xffffffffu, q1, o);
        s2 += __shfl_xor_sync(0xffffffffu, s2, o);
        q2 += __shfl_xor_sync(0xffffffffu, q2, o);
    }
    __shared__ float sh[4][8];
    int w = d >> 5;
    if ((d & 31) == 0) { sh[0][w] = s1; sh[1][w] = q1; sh[2][w] = s2; sh[3][w] = q2; }
    __syncthreads();
    float S1 = 0, Q1 = 0, S2 = 0, Q2 = 0;
#pragma unroll
    for (int i = 0; i < 8; i++) { S1 += sh[0][i]; Q1 += sh[1][i]; S2 += sh[2][i]; Q2 += sh[3][i]; }
    const float invD = 1.0f / 256.0f;
    float mu1 = S1 * invD, mu2 = S2 * invD;
    float var1 = Q1 * invD - mu1 * mu1;
    float var2 = Q2 * invD - mu2 * mu2;
    float r1 = rsqrtf(var1 + 1e-6f);
    float r2 = rsqrtf(var2 + 1e-6f);
    float g = lng[d], bb = lnb[d];
    out[idx] = 0.5f * (((x1 - mu1) * r1 * g + bb) + ((x2 - mu2) * r2 * g + bb));
}

// ---------------- launch ----------------
extern "C" void kernel_launch(void* const* d_in, const int* in_sizes, int n_in,
                              void* d_out, int out_size) {
    (void)in_sizes; (void)n_in; (void)out_size;
    const float* a_fea = (const float*)d_in[0];
    const float* v_fea = (const float*)d_in[1];
    const float* Wv1   = (const float*)d_in[2];
    const float* Wv2   = (const float*)d_in[3];
    const float* Wa1   = (const float*)d_in[4];
    const float* Wa2   = (const float*)d_in[5];
    const float* lng   = (const float*)d_in[6];
    const float* lnb   = (const float*)d_in[7];
    const float* thr   = (const float*)d_in[8];
    float* out = (float*)d_out;

    k_in_gemm<<<dim3(2, 128, 4), 256>>>(v_fea, a_fea, Wv1, Wv2, Wa1, Wa2);
    k_beta_g<<<dim3(16, 16, 8), 256>>>();
    k_sumred<<<NB * NT / 256, 256>>>();
    k_pos<<<dim3(2, 16, 16), 256>>>(thr);
    k_final<<<BT, 256>>>(v_fea, a_fea, lng, lnb, out);
}

// round 3
// speedup vs baseline: 2.3864x; 2.3864x over previous
#include <cuda_runtime.h>

#define NB 8
#define NT 2048
#define ND 256
#define BT (NB*NT)
#define CCAP 12   // hard math bound is 10 events per row/col (sum of normalized vals <= 1)

// ---------------- scratch (static device globals; no allocation) ----------------
__device__ float g_vb1[BT*ND];
__device__ float g_vb2[BT*ND];
__device__ float g_ab1[BT*ND];
__device__ float g_ab2[BT*ND];
__device__ float g_beta[(size_t)NB*NT*NT];     // 134 MB
__device__ float g_rowpart[16*NB*NT];          // per ab-tile partial row sums
__device__ float g_colpart[16*NB*NT];          // per vb-tile partial col sums
__device__ float g_rowsum[NB*NT];
__device__ float g_colsum[NB*NT];
__device__ float g_apos[BT*ND];
__device__ float g_vpos[BT*ND];
__device__ int   g_ccnt[NB*NT*8];              // col-scan event counts per (col, vseg)
__device__ float g_cval[(size_t)NB*NT*8*CCAP];
__device__ int   g_cv[(size_t)NB*NT*8*CCAP];

// ---------------- shared GEMM core: BM=BN=128, BK=16, 256 thr, 8x8 micro ----------------
__device__ __forceinline__ void mm_inner(const float (*As)[132], const float (*Bs)[132],
                                         float acc[8][8], int tx, int ty) {
#pragma unroll
    for (int kk = 0; kk < 16; kk++) {
        float ar[8], br[8];
        *(float4*)&ar[0] = *(const float4*)&As[kk][ty * 4];
        *(float4*)&ar[4] = *(const float4*)&As[kk][64 + ty * 4];
        *(float4*)&br[0] = *(const float4*)&Bs[kk][tx * 4];
        *(float4*)&br[4] = *(const float4*)&Bs[kk][64 + tx * 4];
#pragma unroll
        for (int i = 0; i < 8; i++)
#pragma unroll
            for (int j = 0; j < 8; j++)
                acc[i][j] = fmaf(ar[i], br[j], acc[i][j]);
    }
}

__device__ __forceinline__ void load_T(float (*S)[132], const float* __restrict__ G,
                                       int rowBase, int ld, int k0, int tid) {
    int kk = tid & 15;
    int r0 = tid >> 4;
#pragma unroll
    for (int i = 0; i < 8; i++) {
        int r = r0 + i * 16;
        S[kk][r] = G[(size_t)(rowBase + r) * ld + k0 + kk];
    }
}

__device__ __forceinline__ void load_N(float (*S)[132], const float* __restrict__ G,
                                       int k0, int ld, int nBase, int tid) {
    int n = tid & 127;
    int kb = tid >> 7;
#pragma unroll
    for (int i = 0; i < 8; i++) {
        int kk = kb + i * 2;
        S[kk][n] = G[(size_t)(k0 + kk) * ld + nBase + n];
    }
}

// ---------------- stage 1: four input GEMMs + relu ----------------
__global__ __launch_bounds__(256) void k_in_gemm(const float* __restrict__ vf, const float* __restrict__ af,
                                                 const float* __restrict__ Wv1, const float* __restrict__ Wv2,
                                                 const float* __restrict__ Wa1, const float* __restrict__ Wa2) {
    __shared__ __align__(16) float As[16][132];
    __shared__ __align__(16) float Bs[16][132];
    int z = blockIdx.z;
    const float* X = (z < 2) ? vf : af;
    const float* W = (z == 0) ? Wv1 : (z == 1) ? Wv2 : (z == 2) ? Wa1 : Wa2;
    float* Y = (z == 0) ? g_vb1 : (z == 1) ? g_vb2 : (z == 2) ? g_ab1 : g_ab2;
    int mb = blockIdx.y * 128, nb = blockIdx.x * 128;
    int tid = threadIdx.x, tx = tid & 15, ty = tid >> 4;
    float acc[8][8] = {};
    for (int k0 = 0; k0 < ND; k0 += 16) {
        load_T(As, X, mb, ND, k0, tid);
        load_N(Bs, W, k0, ND, nb, tid);
        __syncthreads();
        mm_inner(As, Bs, acc, tx, ty);
        __syncthreads();
    }
#pragma unroll
    for (int ih = 0; ih < 2; ih++)
#pragma unroll
        for (int i = 0; i < 4; i++) {
            int m = mb + ih * 64 + ty * 4 + i;
#pragma unroll
            for (int jh = 0; jh < 2; jh++) {
                float4 o;
                o.x = fmaxf(acc[ih * 4 + i][jh * 4 + 0], 0.f);
                o.y = fmaxf(acc[ih * 4 + i][jh * 4 + 1], 0.f);
                o.z = fmaxf(acc[ih * 4 + i][jh * 4 + 2], 0.f);
                o.w = fmaxf(acc[ih * 4 + i][jh * 4 + 3], 0.f);
                *(float4*)&Y[(size_t)m * ND + nb + jh * 64 + tx * 4] = o;
            }
        }
}

// ---------------- stage 2: beta = relu((Vb2 @ Ab1^T)/16), fused partial row/col sums ----------------
__global__ __launch_bounds__(256) void k_beta_g() {
    __shared__ __align__(16) float As[16][132];
    __shared__ __align__(16) float Bs[16][132];
    int b = blockIdx.z;
    const float* V = g_vb2 + (size_t)b * NT * ND;
    const float* A = g_ab1 + (size_t)b * NT * ND;
    float* Bo = g_beta + (size_t)b * NT * NT;
    int vb = blockIdx.y * 128, ab = blockIdx.x * 128;
    int tid = threadIdx.x, tx = tid & 15, ty = tid >> 4;
    float acc[8][8] = {};
    for (int k0 = 0; k0 < ND; k0 += 16) {
        load_T(As, V, vb, ND, k0, tid);
        load_T(Bs, A, ab, ND, k0, tid);
        __syncthreads();
        mm_inner(As, Bs, acc, tx, ty);
        __syncthreads();
    }
    const float sc = 0.0625f;  // 1/sqrt(256)
    float rsum[8];
#pragma unroll
    for (int i = 0; i < 8; i++) rsum[i] = 0.f;
#pragma unroll
    for (int ih = 0; ih < 2; ih++)
#pragma unroll
        for (int i = 0; i < 4; i++) {
            int r = ih * 4 + i;
            int m = vb + ih * 64 + ty * 4 + i;
#pragma unroll
            for (int jh = 0; jh < 2; jh++) {
                float4 o;
                o.x = fmaxf(acc[r][jh * 4 + 0] * sc, 0.f);
                o.y = fmaxf(acc[r][jh * 4 + 1] * sc, 0.f);
                o.z = fmaxf(acc[r][jh * 4 + 2] * sc, 0.f);
                o.w = fmaxf(acc[r][jh * 4 + 3] * sc, 0.f);
                acc[r][jh * 4 + 0] = o.x; acc[r][jh * 4 + 1] = o.y;
                acc[r][jh * 4 + 2] = o.z; acc[r][jh * 4 + 3] = o.w;
                rsum[r] += (o.x + o.y) + (o.z + o.w);
                *(float4*)&Bo[(size_t)m * NT + ab + jh * 64 + tx * 4] = o;
            }
        }
    // row partials: reduce across tx (16 lanes)
#pragma unroll
    for (int o = 1; o < 16; o <<= 1)
#pragma unroll
        for (int i = 0; i < 8; i++) rsum[i] += __shfl_xor_sync(0xffffffffu, rsum[i], o);
    if (tx == 0) {
        float* rp = g_rowpart + ((size_t)blockIdx.x * NB + b) * NT + vb;
#pragma unroll
        for (int ih = 0; ih < 2; ih++)
#pragma unroll
            for (int i = 0; i < 4; i++) rp[ih * 64 + ty * 4 + i] = rsum[ih * 4 + i];
    }
    // col partials: smem reduce across ty
    float* scol = &As[0][0];
    __syncthreads();
#pragma unroll
    for (int jh = 0; jh < 2; jh++)
#pragma unroll
        for (int j = 0; j < 4; j++) {
            float s = 0.f;
#pragma unroll
            for (int i = 0; i < 8; i++) s += acc[i][jh * 4 + j];
            scol[ty * 128 + jh * 64 + tx * 4 + j] = s;
        }
    __syncthreads();
    if (tid < 128) {
        float s = 0.f;
#pragma unroll
        for (int t = 0; t < 16; t++) s += scol[t * 128 + tid];
        g_colpart[((size_t)blockIdx.y * NB + b) * NT + ab + tid] = s;
    }
}

// ---------------- stage 2b: final sums (16 partials each) ----------------
__global__ __launch_bounds__(256) void k_sumred() {
    int i = blockIdx.x * 256 + threadIdx.x;
    float r = 0.f, c = 0.f;
#pragma unroll
    for (int t = 0; t < 16; t++) {
        r += g_rowpart[(size_t)t * NB * NT + i];
        c += g_colpart[(size_t)t * NB * NT + i];
    }
    g_rowsum[i] = r;
    g_colsum[i] = c;
}

// ---------------- stage 3a: row scan — a_pos via sparse events (<=10 per row guaranteed) ----------------
__global__ __launch_bounds__(256) void k_rowscan(const float* __restrict__ thr_p) {
    int row = blockIdx.x;           // b*2048 + v
    int b = row >> 11;
    int tid = threadIdx.x;
    float thr = thr_p[0];
    float inv = 1.0f / (g_rowsum[row] + 1e-8f);
    const float* brow = g_beta + (size_t)row * NT;
    const float* AB2 = g_ab2 + (size_t)b * NT * ND;
    float r[8];
#pragma unroll
    for (int c = 0; c < 8; c++) r[c] = brow[c * 256 + tid];   // prefetch, MLP=8
    __shared__ float ev_val[256];
    __shared__ int   ev_a[256];
    __shared__ int   wcnt[8];
    float acc = 0.f;
    int w = tid >> 5, l = tid & 31;
#pragma unroll
    for (int c = 0; c < 8; c++) {
        float nv = r[c] * inv;
        bool p = nv > thr;
        unsigned m = __ballot_sync(0xffffffffu, p);
        if (l == 0) wcnt[w] = __popc(m);
        __syncthreads();
        int off = 0, tot = 0;
#pragma unroll
        for (int i = 0; i < 8; i++) { int cc = wcnt[i]; tot += cc; if (i < w) off += cc; }
        if (p) { int pos = off + __popc(m & ((1u << l) - 1u)); ev_val[pos] = nv; ev_a[pos] = c * 256 + tid; }
        __syncthreads();
        for (int e = 0; e < tot; e++)
            acc = fmaf(ev_val[e], AB2[(size_t)ev_a[e] * ND + tid], acc);
    }
    g_apos[(size_t)row * ND + tid] = acc;
}

// ---------------- stage 3b: col scan phase 1 — per-(col,vseg) events to fixed slots ----------------
__global__ __launch_bounds__(256) void k_colscan(const float* __restrict__ thr_p) {
    int b = blockIdx.z, grp = blockIdx.y, seg = blockIdx.x;
    int tid = threadIdx.x;
    int a = grp * 256 + tid;
    float thr = thr_p[0];
    float inv = 1.0f / (g_colsum[b * NT + a] + 1e-8f);
    const float* base = g_beta + (size_t)b * NT * NT + a;
    size_t slotbase = ((size_t)(b * NT + a) * 8 + seg) * CCAP;
    int cnt = 0;
    int v0 = seg * 256;
#pragma unroll 4
    for (int i = 0; i < 256; i++) {
        int v = v0 + i;
        float nv = base[(size_t)v * NT] * inv;
        if (nv > thr && cnt < CCAP) { g_cval[slotbase + cnt] = nv; g_cv[slotbase + cnt] = v; cnt++; }
    }
    g_ccnt[(b * NT + a) * 8 + seg] = cnt;
}

// ---------------- stage 3c: col merge — v_pos from events (deterministic ascending-v order) ----------------
__global__ __launch_bounds__(256) void k_colmerge() {
    int col = blockIdx.x;           // b*2048 + a
    int b = col >> 11;
    int tid = threadIdx.x;
    const float* VB1 = g_vb1 + (size_t)b * NT * ND;
    float acc = 0.f;
#pragma unroll
    for (int seg = 0; seg < 8; seg++) {
        int c = g_ccnt[col * 8 + seg];
        size_t sb = ((size_t)col * 8 + seg) * CCAP;
        for (int e = 0; e < c; e++)
            acc = fmaf(g_cval[sb + e], VB1[(size_t)g_cv[sb + e] * ND + tid], acc);
    }
    g_vpos[(size_t)col * ND + tid] = acc;
}

// ---------------- stage 4: residual + dual LayerNorm + average ----------------
__global__ __launch_bounds__(256) void k_final(const float* __restrict__ vf, const float* __restrict__ af,
                                               const float* __restrict__ lng, const float* __restrict__ lnb,
                                               float* __restrict__ out) {
    int row = blockIdx.x;
    int d = threadIdx.x;
    size_t idx = (size_t)row * ND + d;
    float x1 = vf[idx] + g_apos[idx];
    float x2 = af[idx] + g_vpos[idx];
    float s1 = x1, q1 = x1 * x1, s2 = x2, q2 = x2 * x2;
#pragma unroll
    for (int o = 16; o; o >>= 1) {
        s1 += __shfl_xor_sync(0xffffffffu, s1, o);
        q1 += __shfl_xor_sync(0xffffffffu, q1, o);
        s2 += __shfl_xor_sync(0xffffffffu, s2, o);
        q2 += __shfl_xor_sync(0xffffffffu, q2, o);
    }
    __shared__ float sh[4][8];
    int w = d >> 5;
    if ((d & 31) == 0) { sh[0][w] = s1; sh[1][w] = q1; sh[2][w] = s2; sh[3][w] = q2; }
    __syncthreads();
    float S1 = 0, Q1 = 0, S2 = 0, Q2 = 0;
#pragma unroll
    for (int i = 0; i < 8; i++) { S1 += sh[0][i]; Q1 += sh[1][i]; S2 += sh[2][i]; Q2 += sh[3][i]; }
    const float invD = 1.0f / 256.0f;
    float mu1 = S1 * invD, mu2 = S2 * invD;
    float var1 = Q1 * invD - mu1 * mu1;
    float var2 = Q2 * invD - mu2 * mu2;
    float r1 = rsqrtf(var1 + 1e-6f);
    float r2 = rsqrtf(var2 + 1e-6f);
    float g = lng[d], bb = lnb[d];
    out[idx] = 0.5f * (((x1 - mu1) * r1 * g + bb) + ((x2 - mu2) * r2 * g + bb));
}

// ---------------- launch ----------------
extern "C" void kernel_launch(void* const* d_in, const int* in_sizes, int n_in,
                              void* d_out, int out_size) {
    (void)in_sizes; (void)n_in; (void)out_size;
    const float* a_fea = (const float*)d_in[0];
    const float* v_fea = (const float*)d_in[1];
    const float* Wv1   = (const float*)d_in[2];
    const float* Wv2   = (const float*)d_in[3];
    const float* Wa1   = (const float*)d_in[4];
    const float* Wa2   = (const float*)d_in[5];
    const float* lng   = (const float*)d_in[6];
    const float* lnb   = (const float*)d_in[7];
    const float* thr   = (const float*)d_in[8];
    float* out = (float*)d_out;

    k_in_gemm<<<dim3(2, 128, 4), 256>>>(v_fea, a_fea, Wv1, Wv2, Wa1, Wa2);
    k_beta_g<<<dim3(16, 16, 8), 256>>>();
    k_sumred<<<NB * NT / 256, 256>>>();
    k_rowscan<<<BT, 256>>>(thr);
    k_colscan<<<dim3(8, 8, 8), 256>>>(thr);
    k_colmerge<<<BT, 256>>>();
    k_final<<<BT, 256>>>(v_fea, a_fea, lng, lnb, out);
}

// round 5
// speedup vs baseline: 3.6102x; 1.5128x over previous
#include <cuda_runtime.h>
#include <cuda_bf16.h>
#include <cstdint>

#define NB 8
#define NT 2048
#define ND 256
#define BT (NB*NT)
#define CCAP 12

// ================= scratch (static device globals; no allocation) =================
__device__ __align__(16) float g_vb1[BT*ND];
__device__ __align__(16) float g_ab2[BT*ND];
__device__ __align__(16) __nv_bfloat16 g_vb2h[BT*ND];
__device__ __align__(16) __nv_bfloat16 g_vb2l[BT*ND];
__device__ __align__(16) __nv_bfloat16 g_ab1h[BT*ND];
__device__ __align__(16) __nv_bfloat16 g_ab1l[BT*ND];
__device__ __align__(16) __nv_bfloat16 g_vfh[BT*ND];
__device__ __align__(16) __nv_bfloat16 g_vfl[BT*ND];
__device__ __align__(16) __nv_bfloat16 g_afh[BT*ND];
__device__ __align__(16) __nv_bfloat16 g_afl[BT*ND];
__device__ __align__(16) __nv_bfloat16 g_wth[4*ND*ND];
__device__ __align__(16) __nv_bfloat16 g_wtl[4*ND*ND];
__device__ float g_beta[(size_t)NB*NT*NT];
__device__ float g_rowpart[16*NB*NT];
__device__ float g_colpart[16*NB*NT];
__device__ float g_rowsum[NB*NT];
__device__ float g_colsum[NB*NT];
__device__ float g_apos[BT*ND];
__device__ float g_vpos[BT*ND];
__device__ int   g_ccnt[NB*NT*8];
__device__ float g_cval[(size_t)NB*NT*8*CCAP];
__device__ int   g_cv[(size_t)NB*NT*8*CCAP];

// ================= PTX helpers =================
__device__ __forceinline__ uint32_t smem_u32(const void* p) {
    uint32_t a;
    asm("{ .reg .u64 t; cvta.to.shared.u64 t, %1; cvt.u32.u64 %0, t; }" : "=r"(a) : "l"(p));
    return a;
}
#define LDMX4(r, addr) \
    asm volatile("ldmatrix.sync.aligned.m8n8.x4.shared.b16 {%0,%1,%2,%3}, [%4];" \
        : "=r"((r)[0]), "=r"((r)[1]), "=r"((r)[2]), "=r"((r)[3]) : "r"(addr))
#define LDMX2(r, addr) \
    asm volatile("ldmatrix.sync.aligned.m8n8.x2.shared.b16 {%0,%1}, [%2];" \
        : "=r"((r)[0]), "=r"((r)[1]) : "r"(addr))
#define MMA_BF16(d, a, b) \
    asm volatile("mma.sync.aligned.m16n8k16.row.col.f32.bf16.bf16.f32 " \
        "{%0,%1,%2,%3}, {%4,%5,%6,%7}, {%8,%9}, {%0,%1,%2,%3};" \
        : "+f"((d)[0]), "+f"((d)[1]), "+f"((d)[2]), "+f"((d)[3]) \
        : "r"((a)[0]), "r"((a)[1]), "r"((a)[2]), "r"((a)[3]), "r"((b)[0]), "r"((b)[1]))

// ================= HMMA GEMM core: D[128m x 128n] = A[128x256]*(B[128x256])^T, bf16x3 =================
// SMEM per buffer: 4 arrays (Ah,Al,Bh,Bl), each 128 rows x 32 bf16, row stride 80B (conflict-free).
#define ROWB 80
#define ARR_SZ (128*ROWB)          // 10240
#define OFF_AH 0
#define OFF_AL (1*ARR_SZ)
#define OFF_BH (2*ARR_SZ)
#define OFF_BL (3*ARR_SZ)
#define BUF_SZ (4*ARR_SZ)          // 40960
#define SMEM_TOTAL (2*BUF_SZ)      // 81920

__device__ __forceinline__ void gemm128(
    const uint4* __restrict__ Ah, const uint4* __restrict__ Al,
    const uint4* __restrict__ Bh, const uint4* __restrict__ Bl,
    char* smem, float acc[4][4][4], int tid)
{
    const int lane = tid & 31, wid = tid >> 5;
    const int wm = wid >> 2, wn = wid & 3;
    uint4 ra[2], rl[2], rb[2], rd[2];
    auto LOAD = [&](int kc) {
#pragma unroll
        for (int i = 0; i < 2; i++) {
            int vec = tid + i * 256;
            int row = vec >> 2, q = vec & 3;
            int gi = row * 32 + kc * 4 + q;
            ra[i] = Ah[gi]; rl[i] = Al[gi]; rb[i] = Bh[gi]; rd[i] = Bl[gi];
        }
    };
    auto STORE = [&](int s) {
        char* buf = smem + s * BUF_SZ;
#pragma unroll
        for (int i = 0; i < 2; i++) {
            int vec = tid + i * 256;
            int row = vec >> 2, q = vec & 3;
            int so = row * ROWB + q * 16;
            *(uint4*)(buf + OFF_AH + so) = ra[i];
            *(uint4*)(buf + OFF_AL + so) = rl[i];
            *(uint4*)(buf + OFF_BH + so) = rb[i];
            *(uint4*)(buf + OFF_BL + so) = rd[i];
        }
    };
    LOAD(0); STORE(0);
    const int t = lane >> 3, rr = lane & 7;
    uint32_t sb = smem_u32(smem);
    uint32_t aoff = sb + (uint32_t)(wm * 64 + (t & 1) * 8 + rr) * ROWB + (t >> 1) * 16;
    uint32_t boff = sb + (uint32_t)(wn * 32 + rr) * ROWB + (t & 1) * 16;
    for (int kc = 0; kc < 8; kc++) {
        __syncthreads();
        if (kc < 7) LOAD(kc + 1);
        uint32_t bufb = (kc & 1) ? BUF_SZ : 0;
#pragma unroll
        for (int ks = 0; ks < 2; ks++) {
            uint32_t afh[4][4], afl[4][4], bfh[4][2], bfl[4][2];
#pragma unroll
            for (int mi = 0; mi < 4; mi++) {
                uint32_t ad = aoff + bufb + mi * (16 * ROWB) + ks * 32;
                LDMX4(afh[mi], ad + OFF_AH);
                LDMX4(afl[mi], ad + OFF_AL);
            }
#pragma unroll
            for (int ni = 0; ni < 4; ni++) {
                uint32_t bd = boff + bufb + ni * (8 * ROWB) + ks * 32;
                LDMX2(bfh[ni], bd + OFF_BH);
                LDMX2(bfl[ni], bd + OFF_BL);
            }
#pragma unroll
            for (int mi = 0; mi < 4; mi++)
#pragma unroll
                for (int ni = 0; ni < 4; ni++) MMA_BF16(acc[mi][ni], afh[mi], bfh[ni]);
#pragma unroll
            for (int mi = 0; mi < 4; mi++)
#pragma unroll
                for (int ni = 0; ni < 4; ni++) MMA_BF16(acc[mi][ni], afh[mi], bfl[ni]);
#pragma unroll
            for (int mi = 0; mi < 4; mi++)
#pragma unroll
                for (int ni = 0; ni < 4; ni++) MMA_BF16(acc[mi][ni], afl[mi], bfh[ni]);
        }
        if (kc < 7) STORE((kc + 1) & 1);
    }
}

// ================= conversions =================
__device__ __forceinline__ void split4(float4 v, uint2& hi, uint2& lo) {
    __nv_bfloat16 h0 = __float2bfloat16(v.x), h1 = __float2bfloat16(v.y);
    __nv_bfloat16 h2 = __float2bfloat16(v.z), h3 = __float2bfloat16(v.w);
    __nv_bfloat16 l0 = __float2bfloat16(v.x - __bfloat162float(h0));
    __nv_bfloat16 l1 = __float2bfloat16(v.y - __bfloat162float(h1));
    __nv_bfloat16 l2 = __float2bfloat16(v.z - __bfloat162float(h2));
    __nv_bfloat16 l3 = __float2bfloat16(v.w - __bfloat162float(h3));
    hi.x = (uint32_t)*(uint16_t*)&h0 | ((uint32_t)*(uint16_t*)&h1 << 16);
    hi.y = (uint32_t)*(uint16_t*)&h2 | ((uint32_t)*(uint16_t*)&h3 << 16);
    lo.x = (uint32_t)*(uint16_t*)&l0 | ((uint32_t)*(uint16_t*)&l1 << 16);
    lo.y = (uint32_t)*(uint16_t*)&l2 | ((uint32_t)*(uint16_t*)&l3 << 16);
}

__global__ __launch_bounds__(256) void k_conv_in(const float4* __restrict__ vf, const float4* __restrict__ af) {
    int i = blockIdx.x * 256 + threadIdx.x;
    uint2 h, l;
    split4(vf[i], h, l);
    ((uint2*)g_vfh)[i] = h; ((uint2*)g_vfl)[i] = l;
    split4(af[i], h, l);
    ((uint2*)g_afh)[i] = h; ((uint2*)g_afl)[i] = l;
}

__global__ __launch_bounds__(256) void k_conv_w(const float* __restrict__ W0, const float* __restrict__ W1,
                                                const float* __restrict__ W2, const float* __restrict__ W3) {
    int lin = blockIdx.x * 256 + threadIdx.x;
    int z = blockIdx.y;
    const float* W = (z == 0) ? W0 : (z == 1) ? W1 : (z == 2) ? W2 : W3;
    int k = lin & 255, n = lin >> 8;
    float v = W[k * 256 + n];
    __nv_bfloat16 h = __float2bfloat16(v);
    __nv_bfloat16 l = __float2bfloat16(v - __bfloat162float(h));
    g_wth[z * 65536 + n * 256 + k] = h;
    g_wtl[z * 65536 + n * 256 + k] = l;
}

// ================= stage 1: input GEMMs + relu (HMMA) =================
__global__ __launch_bounds__(256) void k_hmma_s1() {
    extern __shared__ char smem[];
    int tid = threadIdx.x;
    int nx = blockIdx.x, mt = blockIdx.y, z = blockIdx.z;
    size_t arow = (size_t)mt * 128;
    const uint4* Ah = (const uint4*)((z < 2) ? g_vfh : g_afh) + arow * 32;
    const uint4* Al = (const uint4*)((z < 2) ? g_vfl : g_afl) + arow * 32;
    const uint4* Bh = (const uint4*)g_wth + ((size_t)z * 256 + nx * 128) * 32;
    const uint4* Bl = (const uint4*)g_wtl + ((size_t)z * 256 + nx * 128) * 32;
    float acc[4][4][4] = {};
    gemm128(Ah, Al, Bh, Bl, smem, acc, tid);

    int lane = tid & 31, wid = tid >> 5, wm = wid >> 2, wn = wid & 3;
    int g = lane >> 2, tg = lane & 3;
#pragma unroll
    for (int mi = 0; mi < 4; mi++)
#pragma unroll
        for (int h = 0; h < 2; h++) {
            size_t row = arow + wm * 64 + mi * 16 + g + h * 8;
#pragma unroll
            for (int ni = 0; ni < 4; ni++) {
                int col = nx * 128 + wn * 32 + ni * 8 + tg * 2;
                float d0 = fmaxf(acc[mi][ni][h * 2 + 0], 0.f);
                float d1 = fmaxf(acc[mi][ni][h * 2 + 1], 0.f);
                if (z == 0 || z == 3) {
                    float* Y = (z == 0) ? g_vb1 : g_ab2;
                    *(float2*)&Y[row * ND + col] = make_float2(d0, d1);
                } else {
                    __nv_bfloat16* Yh = (z == 1) ? g_vb2h : g_ab1h;
                    __nv_bfloat16* Yl = (z == 1) ? g_vb2l : g_ab1l;
                    __nv_bfloat16 h0 = __float2bfloat16(d0), h1 = __float2bfloat16(d1);
                    __nv_bfloat16 l0 = __float2bfloat16(d0 - __bfloat162float(h0));
                    __nv_bfloat16 l1 = __float2bfloat16(d1 - __bfloat162float(h1));
                    *(uint32_t*)&Yh[row * ND + col] =
                        (uint32_t)*(uint16_t*)&h0 | ((uint32_t)*(uint16_t*)&h1 << 16);
                    *(uint32_t*)&Yl[row * ND + col] =
                        (uint32_t)*(uint16_t*)&l0 | ((uint32_t)*(uint16_t*)&l1 << 16);
                }
            }
        }
}

// ================= stage 2: beta GEMM + relu/scale + fused row/col partials =================
__global__ __launch_bounds__(256) void k_hmma_s2() {
    extern __shared__ char smem[];
    int tid = threadIdx.x;
    int nt = blockIdx.x, mt = blockIdx.y, b = blockIdx.z;
    size_t arow = (size_t)b * NT + mt * 128;
    size_t brow = (size_t)b * NT + nt * 128;
    const uint4* Ah = (const uint4*)g_vb2h + arow * 32;
    const uint4* Al = (const uint4*)g_vb2l + arow * 32;
    const uint4* Bh = (const uint4*)g_ab1h + brow * 32;
    const uint4* Bl = (const uint4*)g_ab1l + brow * 32;
    float acc[4][4][4] = {};
    gemm128(Ah, Al, Bh, Bl, smem, acc, tid);

    int lane = tid & 31, wid = tid >> 5, wm = wid >> 2, wn = wid & 3;
    int g = lane >> 2, tg = lane & 3;
    float* rowacc = (float*)smem;          // [4][128]
    float* colacc = (float*)smem + 512;    // [2][128]
    const float sc = 0.0625f;
    float* Bo = g_beta + arow * NT + nt * 128;
    float rs[4][2] = {}, cs[4][2] = {};
#pragma unroll
    for (int mi = 0; mi < 4; mi++) {
        int r0 = wm * 64 + mi * 16 + g;
#pragma unroll
        for (int ni = 0; ni < 4; ni++) {
            int c = wn * 32 + ni * 8 + tg * 2;
            float d0 = fmaxf(acc[mi][ni][0] * sc, 0.f);
            float d1 = fmaxf(acc[mi][ni][1] * sc, 0.f);
            float d2 = fmaxf(acc[mi][ni][2] * sc, 0.f);
            float d3 = fmaxf(acc[mi][ni][3] * sc, 0.f);
            *(float2*)&Bo[(size_t)r0 * NT + c] = make_float2(d0, d1);
            *(float2*)&Bo[(size_t)(r0 + 8) * NT + c] = make_float2(d2, d3);
            rs[mi][0] += d0 + d1; rs[mi][1] += d2 + d3;
            cs[ni][0] += d0 + d2; cs[ni][1] += d1 + d3;
        }
    }
#pragma unroll
    for (int mi = 0; mi < 4; mi++)
#pragma unroll
        for (int h = 0; h < 2; h++) {
            float v = rs[mi][h];
            v += __shfl_xor_sync(0xffffffffu, v, 1);
            v += __shfl_xor_sync(0xffffffffu, v, 2);
            if (tg == 0) rowacc[wn * 128 + wm * 64 + mi * 16 + g + h * 8] = v;
        }
#pragma unroll
    for (int ni = 0; ni < 4; ni++)
#pragma unroll
        for (int j = 0; j < 2; j++) {
            float v = cs[ni][j];
            v += __shfl_xor_sync(0xffffffffu, v, 4);
            v += __shfl_xor_sync(0xffffffffu, v, 8);
            v += __shfl_xor_sync(0xffffffffu, v, 16);
            if (lane < 4) colacc[wm * 128 + wn * 32 + ni * 8 + tg * 2 + j] = v;
        }
    __syncthreads();
    if (tid < 128) {
        float r = rowacc[tid] + rowacc[128 + tid] + rowacc[256 + tid] + rowacc[384 + tid];
        g_rowpart[(size_t)nt * NB * NT + b * NT + mt * 128 + tid] = r;
        float c = colacc[tid] + colacc[128 + tid];
        g_colpart[(size_t)mt * NB * NT + b * NT + nt * 128 + tid] = c;
    }
}

// ================= stage 2b: final sums =================
__global__ __launch_bounds__(256) void k_sumred() {
    int i = blockIdx.x * 256 + threadIdx.x;
    float r = 0.f, c = 0.f;
#pragma unroll
    for (int t = 0; t < 16; t++) {
        r += g_rowpart[(size_t)t * NB * NT + i];
        c += g_colpart[(size_t)t * NB * NT + i];
    }
    g_rowsum[i] = r;
    g_colsum[i] = c;
}

// ================= stage 3a: row scan (<=10 events/row guaranteed) =================
__global__ __launch_bounds__(256) void k_rowscan(const float* __restrict__ thr_p) {
    int row = blockIdx.x;
    int b = row >> 11;
    int tid = threadIdx.x;
    float thr = thr_p[0];
    float inv = 1.0f / (g_rowsum[row] + 1e-8f);
    const float* brow = g_beta + (size_t)row * NT;
    const float* AB2 = g_ab2 + (size_t)b * NT * ND;
    float r[8];
#pragma unroll
    for (int c = 0; c < 8; c++) r[c] = brow[c * 256 + tid];
    __shared__ float ev_val[256];
    __shared__ int   ev_a[256];
    __shared__ int   wcnt[8];
    float acc = 0.f;
    int w = tid >> 5, l = tid & 31;
#pragma unroll
    for (int c = 0; c < 8; c++) {
        float nv = r[c] * inv;
        bool p = nv > thr;
        unsigned m = __ballot_sync(0xffffffffu, p);
        if (l == 0) wcnt[w] = __popc(m);
        __syncthreads();
        int off = 0, tot = 0;
#pragma unroll
        for (int i = 0; i < 8; i++) { int cc = wcnt[i]; tot += cc; if (i < w) off += cc; }
        if (p) { int pos = off + __popc(m & ((1u << l) - 1u)); ev_val[pos] = nv; ev_a[pos] = c * 256 + tid; }
        __syncthreads();
        for (int e = 0; e < tot; e++)
            acc = fmaf(ev_val[e], AB2[(size_t)ev_a[e] * ND + tid], acc);
    }
    g_apos[(size_t)row * ND + tid] = acc;
}

// ================= stage 3b: col scan =================
__global__ __launch_bounds__(256) void k_colscan(const float* __restrict__ thr_p) {
    int b = blockIdx.z, grp = blockIdx.y, seg = blockIdx.x;
    int tid = threadIdx.x;
    int a = grp * 256 + tid;
    float thr = thr_p[0];
    float inv = 1.0f / (g_colsum[b * NT + a] + 1e-8f);
    const float* base = g_beta + (size_t)b * NT * NT + a;
    size_t slotbase = ((size_t)(b * NT + a) * 8 + seg) * CCAP;
    int cnt = 0;
    int v0 = seg * 256;
#pragma unroll 4
    for (int i = 0; i < 256; i++) {
        int v = v0 + i;
        float nv = base[(size_t)v * NT] * inv;
        if (nv > thr && cnt < CCAP) { g_cval[slotbase + cnt] = nv; g_cv[slotbase + cnt] = v; cnt++; }
    }
    g_ccnt[(b * NT + a) * 8 + seg] = cnt;
}

// ================= stage 3c: col merge =================
__global__ __launch_bounds__(256) void k_colmerge() {
    int col = blockIdx.x;
    int b = col >> 11;
    int tid = threadIdx.x;
    const float* VB1 = g_vb1 + (size_t)b * NT * ND;
    float acc = 0.f;
#pragma unroll
    for (int seg = 0; seg < 8; seg++) {
        int c = g_ccnt[col * 8 + seg];
        size_t sbse = ((size_t)col * 8 + seg) * CCAP;
        for (int e = 0; e < c; e++)
            acc = fmaf(g_cval[sbse + e], VB1[(size_t)g_cv[sbse + e] * ND + tid], acc);
    }
    g_vpos[(size_t)col * ND + tid] = acc;
}

// ================= stage 4: residual + dual LayerNorm + average =================
__global__ __launch_bounds__(256) void k_final(const float* __restrict__ vf, const float* __restrict__ af,
                                               const float* __restrict__ lng, const float* __restrict__ lnb,
                                               float* __restrict__ out) {
    int row = blockIdx.x;
    int d = threadIdx.x;
    size_t idx = (size_t)row * ND + d;
    float x1 = vf[idx] + g_apos[idx];
    float x2 = af[idx] + g_vpos[idx];
    float s1 = x1, q1 = x1 * x1, s2 = x2, q2 = x2 * x2;
#pragma unroll
    for (int o = 16; o; o >>= 1) {
        s1 += __shfl_xor_sync(0xffffffffu, s1, o);
        q1 += __shfl_xor_sync(0xffffffffu, q1, o);
        s2 += __shfl_xor_sync(0xffffffffu, s2, o);
        q2 += __shfl_xor_sync(0xffffffffu, q2, o);
    }
    __shared__ float sh[4][8];
    int w = d >> 5;
    if ((d & 31) == 0) { sh[0][w] = s1; sh[1][w] = q1; sh[2][w] = s2; sh[3][w] = q2; }
    __syncthreads();
    float S1 = 0, Q1 = 0, S2 = 0, Q2 = 0;
#pragma unroll
    for (int i = 0; i < 8; i++) { S1 += sh[0][i]; Q1 += sh[1][i]; S2 += sh[2][i]; Q2 += sh[3][i]; }
    const float invD = 1.0f / 256.0f;
    float mu1 = S1 * invD, mu2 = S2 * invD;
    float var1 = Q1 * invD - mu1 * mu1;
    float var2 = Q2 * invD - mu2 * mu2;
    float r1 = rsqrtf(var1 + 1e-6f);
    float r2 = rsqrtf(var2 + 1e-6f);
    float gg = lng[d], bb = lnb[d];
    out[idx] = 0.5f * (((x1 - mu1) * r1 * gg + bb) + ((x2 - mu2) * r2 * gg + bb));
}

// ================= launch =================
extern "C" void kernel_launch(void* const* d_in, const int* in_sizes, int n_in,
                              void* d_out, int out_size) {
    (void)in_sizes; (void)n_in; (void)out_size;
    const float* a_fea = (const float*)d_in[0];
    const float* v_fea = (const float*)d_in[1];
    const float* Wv1   = (const float*)d_in[2];
    const float* Wv2   = (const float*)d_in[3];
    const float* Wa1   = (const float*)d_in[4];
    const float* Wa2   = (const float*)d_in[5];
    const float* lng   = (const float*)d_in[6];
    const float* lnb   = (const float*)d_in[7];
    const float* thr   = (const float*)d_in[8];
    float* out = (float*)d_out;

    cudaFuncSetAttribute(k_hmma_s1, cudaFuncAttributeMaxDynamicSharedMemorySize, SMEM_TOTAL);
    cudaFuncSetAttribute(k_hmma_s2, cudaFuncAttributeMaxDynamicSharedMemorySize, SMEM_TOTAL);

    k_conv_in<<<BT * ND / 4 / 256, 256>>>((const float4*)v_fea, (const float4*)a_fea);
    k_conv_w<<<dim3(256, 4), 256>>>(Wv1, Wv2, Wa1, Wa2);
    k_hmma_s1<<<dim3(2, 128, 4), 256, SMEM_TOTAL>>>();
    k_hmma_s2<<<dim3(16, 16, 8), 256, SMEM_TOTAL>>>();
    k_sumred<<<NB * NT / 256, 256>>>();
    k_rowscan<<<BT, 256>>>(thr);
    k_colscan<<<dim3(8, 8, 8), 256>>>(thr);
    k_colmerge<<<BT, 256>>>();
    k_final<<<BT, 256>>>(v_fea, a_fea, lng, lnb, out);
}

// round 6
// speedup vs baseline: 3.9912x; 1.1055x over previous
#include <cuda_runtime.h>
#include <cuda_bf16.h>
#include <cstdint>

#define NB 8
#define NT 2048
#define ND 256
#define BT (NB*NT)
#define CCAP 12

// ================= scratch (static device globals; no allocation) =================
__device__ __align__(16) float g_vb1[BT*ND];
__device__ __align__(16) float g_ab2[BT*ND];
__device__ __align__(16) __nv_bfloat16 g_vb2h[BT*ND];
__device__ __align__(16) __nv_bfloat16 g_vb2l[BT*ND];
__device__ __align__(16) __nv_bfloat16 g_ab1h[BT*ND];
__device__ __align__(16) __nv_bfloat16 g_ab1l[BT*ND];
__device__ __align__(16) __nv_bfloat16 g_vfh[BT*ND];
__device__ __align__(16) __nv_bfloat16 g_vfl[BT*ND];
__device__ __align__(16) __nv_bfloat16 g_afh[BT*ND];
__device__ __align__(16) __nv_bfloat16 g_afl[BT*ND];
__device__ __align__(16) __nv_bfloat16 g_wth[4*ND*ND];
__device__ __align__(16) __nv_bfloat16 g_wtl[4*ND*ND];
__device__ float g_beta[(size_t)NB*NT*NT];
__device__ float g_rowpart[16*NB*NT];
__device__ float g_colpart[16*NB*NT];
__device__ float g_rowsum[NB*NT];
__device__ float g_colsum[NB*NT];
__device__ float g_apos[BT*ND];
__device__ float g_vpos[BT*ND];
__device__ int   g_ccnt[NB*NT*8];
__device__ float g_cval[(size_t)NB*NT*8*CCAP];
__device__ int   g_cv[(size_t)NB*NT*8*CCAP];

// ================= PTX helpers =================
__device__ __forceinline__ uint32_t smem_u32(const void* p) {
    uint32_t a;
    asm("{ .reg .u64 t; cvta.to.shared.u64 t, %1; cvt.u32.u64 %0, t; }" : "=r"(a) : "l"(p));
    return a;
}
#define LDMX4(r, addr) \
    asm volatile("ldmatrix.sync.aligned.m8n8.x4.shared.b16 {%0,%1,%2,%3}, [%4];" \
        : "=r"((r)[0]), "=r"((r)[1]), "=r"((r)[2]), "=r"((r)[3]) : "r"(addr))
#define LDMX2(r, addr) \
    asm volatile("ldmatrix.sync.aligned.m8n8.x2.shared.b16 {%0,%1}, [%2];" \
        : "=r"((r)[0]), "=r"((r)[1]) : "r"(addr))
#define MMA_BF16(d, a, b) \
    asm volatile("mma.sync.aligned.m16n8k16.row.col.f32.bf16.bf16.f32 " \
        "{%0,%1,%2,%3}, {%4,%5,%6,%7}, {%8,%9}, {%0,%1,%2,%3};" \
        : "+f"((d)[0]), "+f"((d)[1]), "+f"((d)[2]), "+f"((d)[3]) \
        : "r"((a)[0]), "r"((a)[1]), "r"((a)[2]), "r"((a)[3]), "r"((b)[0]), "r"((b)[1]))
#define CPA16(dst, src) \
    asm volatile("cp.async.cg.shared.global [%0], [%1], 16;" :: "r"(dst), "l"(src) : "memory")
#define CPA_COMMIT() asm volatile("cp.async.commit_group;" ::: "memory")
#define CPA_WAIT1()  asm volatile("cp.async.wait_group 1;" ::: "memory")
#define CPA_WAIT0()  asm volatile("cp.async.wait_group 0;" ::: "memory")

// ================= HMMA GEMM core: D[128m x 128n] = A[128x256]*(B[128x256])^T, bf16x3 =================
// SMEM per buffer: 4 arrays (Ah,Al,Bh,Bl), each 128 rows x 32 bf16, row stride 80B (conflict-free).
#define ROWB 80
#define ARR_SZ (128*ROWB)          // 10240
#define OFF_AH 0
#define OFF_AL (1*ARR_SZ)
#define OFF_BH (2*ARR_SZ)
#define OFF_BL (3*ARR_SZ)
#define BUF_SZ (4*ARR_SZ)          // 40960
#define SMEM_TOTAL (2*BUF_SZ)      // 81920

__device__ __forceinline__ void gemm128(
    const uint4* __restrict__ Ah, const uint4* __restrict__ Al,
    const uint4* __restrict__ Bh, const uint4* __restrict__ Bl,
    char* smem, float acc[4][4][4], int tid)
{
    const int lane = tid & 31, wid = tid >> 5;
    const int wm = wid >> 2, wn = wid & 3;
    uint32_t sb = smem_u32(smem);
    const int row0 = tid >> 2, q = tid & 3;
    auto COPY = [&](int kc, int s) {
        uint32_t buf = sb + s * BUF_SZ;
#pragma unroll
        for (int i = 0; i < 2; i++) {
            int r = row0 + i * 64;
            int gi = r * 32 + kc * 4 + q;
            uint32_t so = (uint32_t)r * ROWB + q * 16;
            CPA16(buf + OFF_AH + so, Ah + gi);
            CPA16(buf + OFF_AL + so, Al + gi);
            CPA16(buf + OFF_BH + so, Bh + gi);
            CPA16(buf + OFF_BL + so, Bl + gi);
        }
        CPA_COMMIT();
    };
    COPY(0, 0);
    const int t = lane >> 3, rr = lane & 7;
    uint32_t aoff = sb + (uint32_t)(wm * 64 + (t & 1) * 8 + rr) * ROWB + (t >> 1) * 16;
    uint32_t boff = sb + (uint32_t)(wn * 32 + rr) * ROWB + (t & 1) * 16;
    for (int kc = 0; kc < 8; kc++) {
        if (kc < 7) { COPY(kc + 1, (kc + 1) & 1); CPA_WAIT1(); }
        else        { CPA_WAIT0(); }
        __syncthreads();
        uint32_t bufb = (kc & 1) ? BUF_SZ : 0;
#pragma unroll
        for (int ks = 0; ks < 2; ks++) {
            uint32_t afh[4][4], afl[4][4], bfh[4][2], bfl[4][2];
#pragma unroll
            for (int mi = 0; mi < 4; mi++) {
                uint32_t ad = aoff + bufb + mi * (16 * ROWB) + ks * 32;
                LDMX4(afh[mi], ad + OFF_AH);
                LDMX4(afl[mi], ad + OFF_AL);
            }
#pragma unroll
            for (int ni = 0; ni < 4; ni++) {
                uint32_t bd = boff + bufb + ni * (8 * ROWB) + ks * 32;
                LDMX2(bfh[ni], bd + OFF_BH);
                LDMX2(bfl[ni], bd + OFF_BL);
            }
#pragma unroll
            for (int mi = 0; mi < 4; mi++)
#pragma unroll
                for (int ni = 0; ni < 4; ni++) MMA_BF16(acc[mi][ni], afh[mi], bfh[ni]);
#pragma unroll
            for (int mi = 0; mi < 4; mi++)
#pragma unroll
                for (int ni = 0; ni < 4; ni++) MMA_BF16(acc[mi][ni], afh[mi], bfl[ni]);
#pragma unroll
            for (int mi = 0; mi < 4; mi++)
#pragma unroll
                for (int ni = 0; ni < 4; ni++) MMA_BF16(acc[mi][ni], afl[mi], bfh[ni]);
        }
        __syncthreads();
    }
}

// ================= conversions =================
__device__ __forceinline__ void split4(float4 v, uint2& hi, uint2& lo) {
    __nv_bfloat16 h0 = __float2bfloat16(v.x), h1 = __float2bfloat16(v.y);
    __nv_bfloat16 h2 = __float2bfloat16(v.z), h3 = __float2bfloat16(v.w);
    __nv_bfloat16 l0 = __float2bfloat16(v.x - __bfloat162float(h0));
    __nv_bfloat16 l1 = __float2bfloat16(v.y - __bfloat162float(h1));
    __nv_bfloat16 l2 = __float2bfloat16(v.z - __bfloat162float(h2));
    __nv_bfloat16 l3 = __float2bfloat16(v.w - __bfloat162float(h3));
    hi.x = (uint32_t)*(uint16_t*)&h0 | ((uint32_t)*(uint16_t*)&h1 << 16);
    hi.y = (uint32_t)*(uint16_t*)&h2 | ((uint32_t)*(uint16_t*)&h3 << 16);
    lo.x = (uint32_t)*(uint16_t*)&l0 | ((uint32_t)*(uint16_t*)&l1 << 16);
    lo.y = (uint32_t)*(uint16_t*)&l2 | ((uint32_t)*(uint16_t*)&l3 << 16);
}

__global__ __launch_bounds__(256) void k_conv_in(const float4* __restrict__ vf, const float4* __restrict__ af) {
    int i = blockIdx.x * 256 + threadIdx.x;
    uint2 h, l;
    split4(vf[i], h, l);
    ((uint2*)g_vfh)[i] = h; ((uint2*)g_vfl)[i] = l;
    split4(af[i], h, l);
    ((uint2*)g_afh)[i] = h; ((uint2*)g_afl)[i] = l;
}

__global__ __launch_bounds__(256) void k_conv_w(const float* __restrict__ W0, const float* __restrict__ W1,
                                                const float* __restrict__ W2, const float* __restrict__ W3) {
    int lin = blockIdx.x * 256 + threadIdx.x;
    int z = blockIdx.y;
    const float* W = (z == 0) ? W0 : (z == 1) ? W1 : (z == 2) ? W2 : W3;
    int k = lin & 255, n = lin >> 8;
    float v = W[k * 256 + n];
    __nv_bfloat16 h = __float2bfloat16(v);
    __nv_bfloat16 l = __float2bfloat16(v - __bfloat162float(h));
    g_wth[z * 65536 + n * 256 + k] = h;
    g_wtl[z * 65536 + n * 256 + k] = l;
}

// ================= stage 1: input GEMMs + relu (HMMA) =================
__global__ __launch_bounds__(256, 2) void k_hmma_s1() {
    extern __shared__ char smem[];
    int tid = threadIdx.x;
    int nx = blockIdx.x, mt = blockIdx.y, z = blockIdx.z;
    size_t arow = (size_t)mt * 128;
    const uint4* Ah = (const uint4*)((z < 2) ? g_vfh : g_afh) + arow * 32;
    const uint4* Al = (const uint4*)((z < 2) ? g_vfl : g_afl) + arow * 32;
    const uint4* Bh = (const uint4*)g_wth + ((size_t)z * 256 + nx * 128) * 32;
    const uint4* Bl = (const uint4*)g_wtl + ((size_t)z * 256 + nx * 128) * 32;
    float acc[4][4][4] = {};
    gemm128(Ah, Al, Bh, Bl, smem, acc, tid);

    int lane = tid & 31, wid = tid >> 5, wm = wid >> 2, wn = wid & 3;
    int g = lane >> 2, tg = lane & 3;
#pragma unroll
    for (int mi = 0; mi < 4; mi++)
#pragma unroll
        for (int h = 0; h < 2; h++) {
            size_t row = arow + wm * 64 + mi * 16 + g + h * 8;
#pragma unroll
            for (int ni = 0; ni < 4; ni++) {
                int col = nx * 128 + wn * 32 + ni * 8 + tg * 2;
                float d0 = fmaxf(acc[mi][ni][h * 2 + 0], 0.f);
                float d1 = fmaxf(acc[mi][ni][h * 2 + 1], 0.f);
                if (z == 0 || z == 3) {
                    float* Y = (z == 0) ? g_vb1 : g_ab2;
                    *(float2*)&Y[row * ND + col] = make_float2(d0, d1);
                } else {
                    __nv_bfloat16* Yh = (z == 1) ? g_vb2h : g_ab1h;
                    __nv_bfloat16* Yl = (z == 1) ? g_vb2l : g_ab1l;
                    __nv_bfloat16 h0 = __float2bfloat16(d0), h1 = __float2bfloat16(d1);
                    __nv_bfloat16 l0 = __float2bfloat16(d0 - __bfloat162float(h0));
                    __nv_bfloat16 l1 = __float2bfloat16(d1 - __bfloat162float(h1));
                    *(uint32_t*)&Yh[row * ND + col] =
                        (uint32_t)*(uint16_t*)&h0 | ((uint32_t)*(uint16_t*)&h1 << 16);
                    *(uint32_t*)&Yl[row * ND + col] =
                        (uint32_t)*(uint16_t*)&l0 | ((uint32_t)*(uint16_t*)&l1 << 16);
                }
            }
        }
}

// ================= stage 2: beta GEMM + relu/scale + fused row/col partials =================
__global__ __launch_bounds__(256, 2) void k_hmma_s2() {
    extern __shared__ char smem[];
    int tid = threadIdx.x;
    int nt = blockIdx.x, mt = blockIdx.y, b = blockIdx.z;
    size_t arow = (size_t)b * NT + mt * 128;
    size_t brow = (size_t)b * NT + nt * 128;
    const uint4* Ah = (const uint4*)g_vb2h + arow * 32;
    const uint4* Al = (const uint4*)g_vb2l + arow * 32;
    const uint4* Bh = (const uint4*)g_ab1h + brow * 32;
    const uint4* Bl = (const uint4*)g_ab1l + brow * 32;
    float acc[4][4][4] = {};
    gemm128(Ah, Al, Bh, Bl, smem, acc, tid);

    int lane = tid & 31, wid = tid >> 5, wm = wid >> 2, wn = wid & 3;
    int g = lane >> 2, tg = lane & 3;
    float* rowacc = (float*)smem;          // [4][128]
    float* colacc = (float*)smem + 512;    // [2][128]
    const float sc = 0.0625f;
    float* Bo = g_beta + arow * NT + nt * 128;
    float rs[4][2] = {}, cs[4][2] = {};
#pragma unroll
    for (int mi = 0; mi < 4; mi++) {
        int r0 = wm * 64 + mi * 16 + g;
#pragma unroll
        for (int ni = 0; ni < 4; ni++) {
            int c = wn * 32 + ni * 8 + tg * 2;
            float d0 = fmaxf(acc[mi][ni][0] * sc, 0.f);
            float d1 = fmaxf(acc[mi][ni][1] * sc, 0.f);
            float d2 = fmaxf(acc[mi][ni][2] * sc, 0.f);
            float d3 = fmaxf(acc[mi][ni][3] * sc, 0.f);
            *(float2*)&Bo[(size_t)r0 * NT + c] = make_float2(d0, d1);
            *(float2*)&Bo[(size_t)(r0 + 8) * NT + c] = make_float2(d2, d3);
            rs[mi][0] += d0 + d1; rs[mi][1] += d2 + d3;
            cs[ni][0] += d0 + d2; cs[ni][1] += d1 + d3;
        }
    }
#pragma unroll
    for (int mi = 0; mi < 4; mi++)
#pragma unroll
        for (int h = 0; h < 2; h++) {
            float v = rs[mi][h];
            v += __shfl_xor_sync(0xffffffffu, v, 1);
            v += __shfl_xor_sync(0xffffffffu, v, 2);
            if (tg == 0) rowacc[wn * 128 + wm * 64 + mi * 16 + g + h * 8] = v;
        }
#pragma unroll
    for (int ni = 0; ni < 4; ni++)
#pragma unroll
        for (int j = 0; j < 2; j++) {
            float v = cs[ni][j];
            v += __shfl_xor_sync(0xffffffffu, v, 4);
            v += __shfl_xor_sync(0xffffffffu, v, 8);
            v += __shfl_xor_sync(0xffffffffu, v, 16);
            if (lane < 4) colacc[wm * 128 + wn * 32 + ni * 8 + tg * 2 + j] = v;
        }
    __syncthreads();
    if (tid < 128) {
        float r = rowacc[tid] + rowacc[128 + tid] + rowacc[256 + tid] + rowacc[384 + tid];
        g_rowpart[(size_t)nt * NB * NT + b * NT + mt * 128 + tid] = r;
        float c = colacc[tid] + colacc[128 + tid];
        g_colpart[(size_t)mt * NB * NT + b * NT + nt * 128 + tid] = c;
    }
}

// ================= stage 2b: final sums =================
__global__ __launch_bounds__(256) void k_sumred() {
    int i = blockIdx.x * 256 + threadIdx.x;
    float r = 0.f, c = 0.f;
#pragma unroll
    for (int t = 0; t < 16; t++) {
        r += g_rowpart[(size_t)t * NB * NT + i];
        c += g_colpart[(size_t)t * NB * NT + i];
    }
    g_rowsum[i] = r;
    g_colsum[i] = c;
}

// ================= stage 3a: row scan (<=10 events/row guaranteed) =================
__global__ __launch_bounds__(256) void k_rowscan(const float* __restrict__ thr_p) {
    int row = blockIdx.x;
    int b = row >> 11;
    int tid = threadIdx.x;
    float thr = thr_p[0];
    float inv = 1.0f / (g_rowsum[row] + 1e-8f);
    const float* brow = g_beta + (size_t)row * NT;
    const float* AB2 = g_ab2 + (size_t)b * NT * ND;
    float r[8];
#pragma unroll
    for (int c = 0; c < 8; c++) r[c] = brow[c * 256 + tid];
    __shared__ float ev_val[256];
    __shared__ int   ev_a[256];
    __shared__ int   wcnt[8];
    float acc = 0.f;
    int w = tid >> 5, l = tid & 31;
#pragma unroll
    for (int c = 0; c < 8; c++) {
        float nv = r[c] * inv;
        bool p = nv > thr;
        unsigned m = __ballot_sync(0xffffffffu, p);
        if (l == 0) wcnt[w] = __popc(m);
        __syncthreads();
        int off = 0, tot = 0;
#pragma unroll
        for (int i = 0; i < 8; i++) { int cc = wcnt[i]; tot += cc; if (i < w) off += cc; }
        if (p) { int pos = off + __popc(m & ((1u << l) - 1u)); ev_val[pos] = nv; ev_a[pos] = c * 256 + tid; }
        __syncthreads();
        for (int e = 0; e < tot; e++)
            acc = fmaf(ev_val[e], AB2[(size_t)ev_a[e] * ND + tid], acc);
    }
    g_apos[(size_t)row * ND + tid] = acc;
}

// ================= stage 3b: col scan =================
__global__ __launch_bounds__(256) void k_colscan(const float* __restrict__ thr_p) {
    int b = blockIdx.z, grp = blockIdx.y, seg = blockIdx.x;
    int tid = threadIdx.x;
    int a = grp * 256 + tid;
    float thr = thr_p[0];
    float inv = 1.0f / (g_colsum[b * NT + a] + 1e-8f);
    const float* base = g_beta + (size_t)b * NT * NT + a;
    size_t slotbase = ((size_t)(b * NT + a) * 8 + seg) * CCAP;
    int cnt = 0;
    int v0 = seg * 256;
#pragma unroll 4
    for (int i = 0; i < 256; i++) {
        int v = v0 + i;
        float nv = base[(size_t)v * NT] * inv;
        if (nv > thr && cnt < CCAP) { g_cval[slotbase + cnt] = nv; g_cv[slotbase + cnt] = v; cnt++; }
    }
    g_ccnt[(b * NT + a) * 8 + seg] = cnt;
}

// ================= stage 3c: col merge =================
__global__ __launch_bounds__(256) void k_colmerge() {
    int col = blockIdx.x;
    int b = col >> 11;
    int tid = threadIdx.x;
    const float* VB1 = g_vb1 + (size_t)b * NT * ND;
    float acc = 0.f;
#pragma unroll
    for (int seg = 0; seg < 8; seg++) {
        int c = g_ccnt[col * 8 + seg];
        size_t sbse = ((size_t)col * 8 + seg) * CCAP;
        for (int e = 0; e < c; e++)
            acc = fmaf(g_cval[sbse + e], VB1[(size_t)g_cv[sbse + e] * ND + tid], acc);
    }
    g_vpos[(size_t)col * ND + tid] = acc;
}

// ================= stage 4: residual + dual LayerNorm + average =================
__global__ __launch_bounds__(256) void k_final(const float* __restrict__ vf, const float* __restrict__ af,
                                               const float* __restrict__ lng, const float* __restrict__ lnb,
                                               float* __restrict__ out) {
    int row = blockIdx.x;
    int d = threadIdx.x;
    size_t idx = (size_t)row * ND + d;
    float x1 = vf[idx] + g_apos[idx];
    float x2 = af[idx] + g_vpos[idx];
    float s1 = x1, q1 = x1 * x1, s2 = x2, q2 = x2 * x2;
#pragma unroll
    for (int o = 16; o; o >>= 1) {
        s1 += __shfl_xor_sync(0xffffffffu, s1, o);
        q1 += __shfl_xor_sync(0xffffffffu, q1, o);
        s2 += __shfl_xor_sync(0xffffffffu, s2, o);
        q2 += __shfl_xor_sync(0xffffffffu, q2, o);
    }
    __shared__ float sh[4][8];
    int w = d >> 5;
    if ((d & 31) == 0) { sh[0][w] = s1; sh[1][w] = q1; sh[2][w] = s2; sh[3][w] = q2; }
    __syncthreads();
    float S1 = 0, Q1 = 0, S2 = 0, Q2 = 0;
#pragma unroll
    for (int i = 0; i < 8; i++) { S1 += sh[0][i]; Q1 += sh[1][i]; S2 += sh[2][i]; Q2 += sh[3][i]; }
    const float invD = 1.0f / 256.0f;
    float mu1 = S1 * invD, mu2 = S2 * invD;
    float var1 = Q1 * invD - mu1 * mu1;
    float var2 = Q2 * invD - mu2 * mu2;
    float r1 = rsqrtf(var1 + 1e-6f);
    float r2 = rsqrtf(var2 + 1e-6f);
    float gg = lng[d], bb = lnb[d];
    out[idx] = 0.5f * (((x1 - mu1) * r1 * gg + bb) + ((x2 - mu2) * r2 * gg + bb));
}

// ================= launch =================
extern "C" void kernel_launch(void* const* d_in, const int* in_sizes, int n_in,
                              void* d_out, int out_size) {
    (void)in_sizes; (void)n_in; (void)out_size;
    const float* a_fea = (const float*)d_in[0];
    const float* v_fea = (const float*)d_in[1];
    const float* Wv1   = (const float*)d_in[2];
    const float* Wv2   = (const float*)d_in[3];
    const float* Wa1   = (const float*)d_in[4];
    const float* Wa2   = (const float*)d_in[5];
    const float* lng   = (const float*)d_in[6];
    const float* lnb   = (const float*)d_in[7];
    const float* thr   = (const float*)d_in[8];
    float* out = (float*)d_out;

    cudaFuncSetAttribute(k_hmma_s1, cudaFuncAttributeMaxDynamicSharedMemorySize, SMEM_TOTAL);
    cudaFuncSetAttribute(k_hmma_s2, cudaFuncAttributeMaxDynamicSharedMemorySize, SMEM_TOTAL);

    k_conv_in<<<BT * ND / 4 / 256, 256>>>((const float4*)v_fea, (const float4*)a_fea);
    k_conv_w<<<dim3(256, 4), 256>>>(Wv1, Wv2, Wa1, Wa2);
    k_hmma_s1<<<dim3(2, 128, 4), 256, SMEM_TOTAL>>>();
    k_hmma_s2<<<dim3(16, 16, 8), 256, SMEM_TOTAL>>>();
    k_sumred<<<NB * NT / 256, 256>>>();
    k_rowscan<<<BT, 256>>>(thr);
    k_colscan<<<dim3(8, 8, 8), 256>>>(thr);
    k_colmerge<<<BT, 256>>>();
    k_final<<<BT, 256>>>(v_fea, a_fea, lng, lnb, out);
}

// round 7
// speedup vs baseline: 4.1388x; 1.0370x over previous
#include <cuda_runtime.h>
#include <cuda_bf16.h>
#include <cstdint>

#define NB 8
#define NT 2048
#define ND 256
#define BT (NB*NT)
#define CCAP 12

// ================= scratch (static device globals; no allocation) =================
__device__ __align__(16) float g_vb1[BT*ND];
__device__ __align__(16) float g_ab2[BT*ND];
__device__ __align__(16) __nv_bfloat16 g_vb2h[BT*ND];
__device__ __align__(16) __nv_bfloat16 g_vb2l[BT*ND];
__device__ __align__(16) __nv_bfloat16 g_ab1h[BT*ND];
__device__ __align__(16) __nv_bfloat16 g_ab1l[BT*ND];
__device__ __align__(16) __nv_bfloat16 g_vfh[BT*ND];
__device__ __align__(16) __nv_bfloat16 g_vfl[BT*ND];
__device__ __align__(16) __nv_bfloat16 g_afh[BT*ND];
__device__ __align__(16) __nv_bfloat16 g_afl[BT*ND];
__device__ __align__(16) __nv_bfloat16 g_wth[4*ND*ND];
__device__ __align__(16) __nv_bfloat16 g_wtl[4*ND*ND];
__device__ float g_beta[(size_t)NB*NT*NT];
__device__ float g_rowpart[16*NB*NT];
__device__ float g_colpart[16*NB*NT];
__device__ float g_rowsum[NB*NT];
__device__ float g_colsum[NB*NT];
__device__ float g_apos[BT*ND];
__device__ float g_vpos[BT*ND];
__device__ int   g_ccnt[NB*NT*8];
__device__ float g_cval[(size_t)NB*NT*8*CCAP];
__device__ int   g_cv[(size_t)NB*NT*8*CCAP];

// ================= PTX helpers =================
__device__ __forceinline__ uint32_t smem_u32(const void* p) {
    uint32_t a;
    asm("{ .reg .u64 t; cvta.to.shared.u64 t, %1; cvt.u32.u64 %0, t; }" : "=r"(a) : "l"(p));
    return a;
}
#define LDMX4(r, addr) \
    asm volatile("ldmatrix.sync.aligned.m8n8.x4.shared.b16 {%0,%1,%2,%3}, [%4];" \
        : "=r"((r)[0]), "=r"((r)[1]), "=r"((r)[2]), "=r"((r)[3]) : "r"(addr))
#define LDMX2(r, addr) \
    asm volatile("ldmatrix.sync.aligned.m8n8.x2.shared.b16 {%0,%1}, [%2];" \
        : "=r"((r)[0]), "=r"((r)[1]) : "r"(addr))
#define MMA_BF16(d, a, b) \
    asm volatile("mma.sync.aligned.m16n8k16.row.col.f32.bf16.bf16.f32 " \
        "{%0,%1,%2,%3}, {%4,%5,%6,%7}, {%8,%9}, {%0,%1,%2,%3};" \
        : "+f"((d)[0]), "+f"((d)[1]), "+f"((d)[2]), "+f"((d)[3]) \
        : "r"((a)[0]), "r"((a)[1]), "r"((a)[2]), "r"((a)[3]), "r"((b)[0]), "r"((b)[1]))
#define CPA16(dst, src) \
    asm volatile("cp.async.cg.shared.global [%0], [%1], 16;" :: "r"(dst), "l"(src) : "memory")
#define CPA_COMMIT() asm volatile("cp.async.commit_group;" ::: "memory")
#define CPA_WAIT0()  asm volatile("cp.async.wait_group 0;" ::: "memory")

// ================= HMMA GEMM core: D[128m x 128n] = A[128x256]*(B[128x256])^T, bf16x3 =================
// SMEM per buffer: 4 arrays (Ah,Al,Bh,Bl), each 128 rows x 32 bf16, row stride 80B (conflict-free).
#define ROWB 80
#define ARR_SZ (128*ROWB)          // 10240
#define OFF_AH 0
#define OFF_AL (1*ARR_SZ)
#define OFF_BH (2*ARR_SZ)
#define OFF_BL (3*ARR_SZ)
#define BUF_SZ (4*ARR_SZ)          // 40960
#define SMEM_TOTAL (2*BUF_SZ)      // 81920

__device__ __forceinline__ void gemm128(
    const uint4* __restrict__ Ah, const uint4* __restrict__ Al,
    const uint4* __restrict__ Bh, const uint4* __restrict__ Bl,
    char* smem, float acc[4][4][4], int tid)
{
    const int lane = tid & 31, wid = tid >> 5;
    const int wm = wid >> 2, wn = wid & 3;
    uint32_t sb = smem_u32(smem);
    const int row0 = tid >> 2, q = tid & 3;
    auto COPY = [&](int kc, int s) {
        uint32_t buf = sb + s * BUF_SZ;
#pragma unroll
        for (int i = 0; i < 2; i++) {
            int r = row0 + i * 64;
            int gi = r * 32 + kc * 4 + q;
            uint32_t so = (uint32_t)r * ROWB + q * 16;
            CPA16(buf + OFF_AH + so, Ah + gi);
            CPA16(buf + OFF_AL + so, Al + gi);
            CPA16(buf + OFF_BH + so, Bh + gi);
            CPA16(buf + OFF_BL + so, Bl + gi);
        }
        CPA_COMMIT();
    };
    COPY(0, 0);
    const int t = lane >> 3, rr = lane & 7;
    uint32_t aoff = sb + (uint32_t)(wm * 64 + (t & 1) * 8 + rr) * ROWB + (t >> 1) * 16;
    uint32_t boff = sb + (uint32_t)(wn * 32 + rr) * ROWB + (t & 1) * 16;
    for (int kc = 0; kc < 8; kc++) {
        // single barrier per chunk: publishes buffer kc (after wait) AND guarantees
        // everyone finished reading the other buffer before COPY overwrites it.
        CPA_WAIT0();
        __syncthreads();
        if (kc < 7) COPY(kc + 1, (kc + 1) & 1);
        uint32_t bufb = (kc & 1) ? BUF_SZ : 0;
#pragma unroll
        for (int ks = 0; ks < 2; ks++) {
            uint32_t afh[4][4], afl[4][4], bfh[4][2], bfl[4][2];
#pragma unroll
            for (int mi = 0; mi < 4; mi++) {
                uint32_t ad = aoff + bufb + mi * (16 * ROWB) + ks * 32;
                LDMX4(afh[mi], ad + OFF_AH);
                LDMX4(afl[mi], ad + OFF_AL);
            }
#pragma unroll
            for (int ni = 0; ni < 4; ni++) {
                uint32_t bd = boff + bufb + ni * (8 * ROWB) + ks * 32;
                LDMX2(bfh[ni], bd + OFF_BH);
                LDMX2(bfl[ni], bd + OFF_BL);
            }
#pragma unroll
            for (int mi = 0; mi < 4; mi++)
#pragma unroll
                for (int ni = 0; ni < 4; ni++) MMA_BF16(acc[mi][ni], afh[mi], bfh[ni]);
#pragma unroll
            for (int mi = 0; mi < 4; mi++)
#pragma unroll
                for (int ni = 0; ni < 4; ni++) MMA_BF16(acc[mi][ni], afh[mi], bfl[ni]);
#pragma unroll
            for (int mi = 0; mi < 4; mi++)
#pragma unroll
                for (int ni = 0; ni < 4; ni++) MMA_BF16(acc[mi][ni], afl[mi], bfh[ni]);
        }
    }
    __syncthreads();   // protect buffer-0 smem region for epilogue reuse
}

// ================= conversions =================
__device__ __forceinline__ void split4(float4 v, uint2& hi, uint2& lo) {
    __nv_bfloat16 h0 = __float2bfloat16(v.x), h1 = __float2bfloat16(v.y);
    __nv_bfloat16 h2 = __float2bfloat16(v.z), h3 = __float2bfloat16(v.w);
    __nv_bfloat16 l0 = __float2bfloat16(v.x - __bfloat162float(h0));
    __nv_bfloat16 l1 = __float2bfloat16(v.y - __bfloat162float(h1));
    __nv_bfloat16 l2 = __float2bfloat16(v.z - __bfloat162float(h2));
    __nv_bfloat16 l3 = __float2bfloat16(v.w - __bfloat162float(h3));
    hi.x = (uint32_t)*(uint16_t*)&h0 | ((uint32_t)*(uint16_t*)&h1 << 16);
    hi.y = (uint32_t)*(uint16_t*)&h2 | ((uint32_t)*(uint16_t*)&h3 << 16);
    lo.x = (uint32_t)*(uint16_t*)&l0 | ((uint32_t)*(uint16_t*)&l1 << 16);
    lo.y = (uint32_t)*(uint16_t*)&l2 | ((uint32_t)*(uint16_t*)&l3 << 16);
}

__global__ __launch_bounds__(256) void k_conv_in(const float4* __restrict__ vf, const float4* __restrict__ af) {
    int i = blockIdx.x * 256 + threadIdx.x;
    uint2 h, l;
    split4(vf[i], h, l);
    ((uint2*)g_vfh)[i] = h; ((uint2*)g_vfl)[i] = l;
    split4(af[i], h, l);
    ((uint2*)g_afh)[i] = h; ((uint2*)g_afl)[i] = l;
}

__global__ __launch_bounds__(256) void k_conv_w(const float* __restrict__ W0, const float* __restrict__ W1,
                                                const float* __restrict__ W2, const float* __restrict__ W3) {
    int lin = blockIdx.x * 256 + threadIdx.x;
    int z = blockIdx.y;
    const float* W = (z == 0) ? W0 : (z == 1) ? W1 : (z == 2) ? W2 : W3;
    int k = lin & 255, n = lin >> 8;
    float v = W[k * 256 + n];
    __nv_bfloat16 h = __float2bfloat16(v);
    __nv_bfloat16 l = __float2bfloat16(v - __bfloat162float(h));
    g_wth[z * 65536 + n * 256 + k] = h;
    g_wtl[z * 65536 + n * 256 + k] = l;
}

// ================= stage 1: input GEMMs + relu (HMMA) =================
__global__ __launch_bounds__(256, 2) void k_hmma_s1() {
    extern __shared__ char smem[];
    int tid = threadIdx.x;
    int nx = blockIdx.x, mt = blockIdx.y, z = blockIdx.z;
    size_t arow = (size_t)mt * 128;
    const uint4* Ah = (const uint4*)((z < 2) ? g_vfh : g_afh) + arow * 32;
    const uint4* Al = (const uint4*)((z < 2) ? g_vfl : g_afl) + arow * 32;
    const uint4* Bh = (const uint4*)g_wth + ((size_t)z * 256 + nx * 128) * 32;
    const uint4* Bl = (const uint4*)g_wtl + ((size_t)z * 256 + nx * 128) * 32;
    float acc[4][4][4] = {};
    gemm128(Ah, Al, Bh, Bl, smem, acc, tid);

    int lane = tid & 31, wid = tid >> 5, wm = wid >> 2, wn = wid & 3;
    int g = lane >> 2, tg = lane & 3;
#pragma unroll
    for (int mi = 0; mi < 4; mi++)
#pragma unroll
        for (int h = 0; h < 2; h++) {
            size_t row = arow + wm * 64 + mi * 16 + g + h * 8;
#pragma unroll
            for (int ni = 0; ni < 4; ni++) {
                int col = nx * 128 + wn * 32 + ni * 8 + tg * 2;
                float d0 = fmaxf(acc[mi][ni][h * 2 + 0], 0.f);
                float d1 = fmaxf(acc[mi][ni][h * 2 + 1], 0.f);
                if (z == 0 || z == 3) {
                    float* Y = (z == 0) ? g_vb1 : g_ab2;
                    *(float2*)&Y[row * ND + col] = make_float2(d0, d1);
                } else {
                    __nv_bfloat16* Yh = (z == 1) ? g_vb2h : g_ab1h;
                    __nv_bfloat16* Yl = (z == 1) ? g_vb2l : g_ab1l;
                    __nv_bfloat16 h0 = __float2bfloat16(d0), h1 = __float2bfloat16(d1);
                    __nv_bfloat16 l0 = __float2bfloat16(d0 - __bfloat162float(h0));
                    __nv_bfloat16 l1 = __float2bfloat16(d1 - __bfloat162float(h1));
                    *(uint32_t*)&Yh[row * ND + col] =
                        (uint32_t)*(uint16_t*)&h0 | ((uint32_t)*(uint16_t*)&h1 << 16);
                    *(uint32_t*)&Yl[row * ND + col] =
                        (uint32_t)*(uint16_t*)&l0 | ((uint32_t)*(uint16_t*)&l1 << 16);
                }
            }
        }
}

// ================= stage 2: beta GEMM + relu/scale + fused row/col partials =================
__global__ __launch_bounds__(256, 2) void k_hmma_s2() {
    extern __shared__ char smem[];
    int tid = threadIdx.x;
    int nt = blockIdx.x, mt = blockIdx.y, b = blockIdx.z;
    size_t arow = (size_t)b * NT + mt * 128;
    size_t brow = (size_t)b * NT + nt * 128;
    const uint4* Ah = (const uint4*)g_vb2h + arow * 32;
    const uint4* Al = (const uint4*)g_vb2l + arow * 32;
    const uint4* Bh = (const uint4*)g_ab1h + brow * 32;
    const uint4* Bl = (const uint4*)g_ab1l + brow * 32;
    float acc[4][4][4] = {};
    gemm128(Ah, Al, Bh, Bl, smem, acc, tid);

    int lane = tid & 31, wid = tid >> 5, wm = wid >> 2, wn = wid & 3;
    int g = lane >> 2, tg = lane & 3;
    float* rowacc = (float*)smem;          // [4][128]
    float* colacc = (float*)smem + 512;    // [2][128]
    const float sc = 0.0625f;
    float* Bo = g_beta + arow * NT + nt * 128;
    float rs[4][2] = {}, cs[4][2] = {};
#pragma unroll
    for (int mi = 0; mi < 4; mi++) {
        int r0 = wm * 64 + mi * 16 + g;
#pragma unroll
        for (int ni = 0; ni < 4; ni++) {
            int c = wn * 32 + ni * 8 + tg * 2;
            float d0 = fmaxf(acc[mi][ni][0] * sc, 0.f);
            float d1 = fmaxf(acc[mi][ni][1] * sc, 0.f);
            float d2 = fmaxf(acc[mi][ni][2] * sc, 0.f);
            float d3 = fmaxf(acc[mi][ni][3] * sc, 0.f);
            *(float2*)&Bo[(size_t)r0 * NT + c] = make_float2(d0, d1);
            *(float2*)&Bo[(size_t)(r0 + 8) * NT + c] = make_float2(d2, d3);
            rs[mi][0] += d0 + d1; rs[mi][1] += d2 + d3;
            cs[ni][0] += d0 + d2; cs[ni][1] += d1 + d3;
        }
    }
#pragma unroll
    for (int mi = 0; mi < 4; mi++)
#pragma unroll
        for (int h = 0; h < 2; h++) {
            float v = rs[mi][h];
            v += __shfl_xor_sync(0xffffffffu, v, 1);
            v += __shfl_xor_sync(0xffffffffu, v, 2);
            if (tg == 0) rowacc[wn * 128 + wm * 64 + mi * 16 + g + h * 8] = v;
        }
#pragma unroll
    for (int ni = 0; ni < 4; ni++)
#pragma unroll
        for (int j = 0; j < 2; j++) {
            float v = cs[ni][j];
            v += __shfl_xor_sync(0xffffffffu, v, 4);
            v += __shfl_xor_sync(0xffffffffu, v, 8);
            v += __shfl_xor_sync(0xffffffffu, v, 16);
            if (lane < 4) colacc[wm * 128 + wn * 32 + ni * 8 + tg * 2 + j] = v;
        }
    __syncthreads();
    if (tid < 128) {
        float r = rowacc[tid] + rowacc[128 + tid] + rowacc[256 + tid] + rowacc[384 + tid];
        g_rowpart[(size_t)nt * NB * NT + b * NT + mt * 128 + tid] = r;
        float c = colacc[tid] + colacc[128 + tid];
        g_colpart[(size_t)mt * NB * NT + b * NT + nt * 128 + tid] = c;
    }
}

// ================= stage 2b: final sums =================
__global__ __launch_bounds__(256) void k_sumred() {
    int i = blockIdx.x * 256 + threadIdx.x;
    float r = 0.f, c = 0.f;
#pragma unroll
    for (int t = 0; t < 16; t++) {
        r += g_rowpart[(size_t)t * NB * NT + i];
        c += g_colpart[(size_t)t * NB * NT + i];
    }
    g_rowsum[i] = r;
    g_colsum[i] = c;
}

// ================= stage 3a: row scan — warp per row, no block barriers =================
__global__ __launch_bounds__(256) void k_rowscan(const float* __restrict__ thr_p) {
    int wid = threadIdx.x >> 5, lane = threadIdx.x & 31;
    int row = blockIdx.x * 8 + wid;
    int b = row >> 11;
    float thr = thr_p[0];
    float inv = 1.0f / (g_rowsum[row] + 1e-8f);
    const float* brow = g_beta + (size_t)row * NT;
    const float* AB2 = g_ab2 + (size_t)b * NT * ND;
    float acc[8] = {};
#pragma unroll
    for (int c8 = 0; c8 < 8; c8++) {
        float v[8];
#pragma unroll
        for (int j = 0; j < 8; j++) v[j] = brow[c8 * 256 + j * 32 + lane];
#pragma unroll
        for (int j = 0; j < 8; j++) {
            float nv = v[j] * inv;
            unsigned m = __ballot_sync(0xffffffffu, nv > thr);
            while (m) {
                int src = __ffs(m) - 1;
                m &= m - 1;
                float val = __shfl_sync(0xffffffffu, nv, src);
                int a = c8 * 256 + j * 32 + src;
#pragma unroll
                for (int q2 = 0; q2 < 8; q2++)
                    acc[q2] = fmaf(val, AB2[(size_t)a * ND + q2 * 32 + lane], acc[q2]);
            }
        }
    }
#pragma unroll
    for (int q2 = 0; q2 < 8; q2++) g_apos[(size_t)row * ND + q2 * 32 + lane] = acc[q2];
}

// ================= stage 3b: col scan =================
__global__ __launch_bounds__(256) void k_colscan(const float* __restrict__ thr_p) {
    int b = blockIdx.z, grp = blockIdx.y, seg = blockIdx.x;
    int tid = threadIdx.x;
    int a = grp * 256 + tid;
    float thr = thr_p[0];
    float inv = 1.0f / (g_colsum[b * NT + a] + 1e-8f);
    const float* base = g_beta + (size_t)b * NT * NT + a;
    size_t slotbase = ((size_t)(b * NT + a) * 8 + seg) * CCAP;
    int cnt = 0;
    int v0 = seg * 256;
#pragma unroll 4
    for (int i = 0; i < 256; i++) {
        int v = v0 + i;
        float nv = base[(size_t)v * NT] * inv;
        if (nv > thr && cnt < CCAP) { g_cval[slotbase + cnt] = nv; g_cv[slotbase + cnt] = v; cnt++; }
    }
    g_ccnt[(b * NT + a) * 8 + seg] = cnt;
}

// ================= stage 3c: col merge =================
__global__ __launch_bounds__(256) void k_colmerge() {
    int col = blockIdx.x;
    int b = col >> 11;
    int tid = threadIdx.x;
    const float* VB1 = g_vb1 + (size_t)b * NT * ND;
    float acc = 0.f;
#pragma unroll
    for (int seg = 0; seg < 8; seg++) {
        int c = g_ccnt[col * 8 + seg];
        size_t sbse = ((size_t)col * 8 + seg) * CCAP;
        for (int e = 0; e < c; e++)
            acc = fmaf(g_cval[sbse + e], VB1[(size_t)g_cv[sbse + e] * ND + tid], acc);
    }
    g_vpos[(size_t)col * ND + tid] = acc;
}

// ================= stage 4: residual + dual LayerNorm + average =================
__global__ __launch_bounds__(256) void k_final(const float* __restrict__ vf, const float* __restrict__ af,
                                               const float* __restrict__ lng, const float* __restrict__ lnb,
                                               float* __restrict__ out) {
    int row = blockIdx.x;
    int d = threadIdx.x;
    size_t idx = (size_t)row * ND + d;
    float x1 = vf[idx] + g_apos[idx];
    float x2 = af[idx] + g_vpos[idx];
    float s1 = x1, q1 = x1 * x1, s2 = x2, q2 = x2 * x2;
#pragma unroll
    for (int o = 16; o; o >>= 1) {
        s1 += __shfl_xor_sync(0xffffffffu, s1, o);
        q1 += __shfl_xor_sync(0xffffffffu, q1, o);
        s2 += __shfl_xor_sync(0xffffffffu, s2, o);
        q2 += __shfl_xor_sync(0xffffffffu, q2, o);
    }
    __shared__ float sh[4][8];
    int w = d >> 5;
    if ((d & 31) == 0) { sh[0][w] = s1; sh[1][w] = q1; sh[2][w] = s2; sh[3][w] = q2; }
    __syncthreads();
    float S1 = 0, Q1 = 0, S2 = 0, Q2 = 0;
#pragma unroll
    for (int i = 0; i < 8; i++) { S1 += sh[0][i]; Q1 += sh[1][i]; S2 += sh[2][i]; Q2 += sh[3][i]; }
    const float invD = 1.0f / 256.0f;
    float mu1 = S1 * invD, mu2 = S2 * invD;
    float var1 = Q1 * invD - mu1 * mu1;
    float var2 = Q2 * invD - mu2 * mu2;
    float r1 = rsqrtf(var1 + 1e-6f);
    float r2 = rsqrtf(var2 + 1e-6f);
    float gg = lng[d], bb = lnb[d];
    out[idx] = 0.5f * (((x1 - mu1) * r1 * gg + bb) + ((x2 - mu2) * r2 * gg + bb));
}

// ================= launch =================
extern "C" void kernel_launch(void* const* d_in, const int* in_sizes, int n_in,
                              void* d_out, int out_size) {
    (void)in_sizes; (void)n_in; (void)out_size;
    const float* a_fea = (const float*)d_in[0];
    const float* v_fea = (const float*)d_in[1];
    const float* Wv1   = (const float*)d_in[2];
    const float* Wv2   = (const float*)d_in[3];
    const float* Wa1   = (const float*)d_in[4];
    const float* Wa2   = (const float*)d_in[5];
    const float* lng   = (const float*)d_in[6];
    const float* lnb   = (const float*)d_in[7];
    const float* thr   = (const float*)d_in[8];
    float* out = (float*)d_out;

    cudaFuncSetAttribute(k_hmma_s1, cudaFuncAttributeMaxDynamicSharedMemorySize, SMEM_TOTAL);
    cudaFuncSetAttribute(k_hmma_s2, cudaFuncAttributeMaxDynamicSharedMemorySize, SMEM_TOTAL);

    k_conv_in<<<BT * ND / 4 / 256, 256>>>((const float4*)v_fea, (const float4*)a_fea);
    k_conv_w<<<dim3(256, 4), 256>>>(Wv1, Wv2, Wa1, Wa2);
    k_hmma_s1<<<dim3(2, 128, 4), 256, SMEM_TOTAL>>>();
    k_hmma_s2<<<dim3(16, 16, 8), 256, SMEM_TOTAL>>>();
    k_sumred<<<NB * NT / 256, 256>>>();
    k_rowscan<<<BT / 8, 256>>>(thr);
    k_colscan<<<dim3(8, 8, 8), 256>>>(thr);
    k_colmerge<<<BT, 256>>>();
    k_final<<<BT, 256>>>(v_fea, a_fea, lng, lnb, out);
}